// round 2
// baseline (speedup 1.0000x reference)
#include <cuda_runtime.h>

// Problem constants
#define B_  16
#define D_  256
#define T_  2048
#define N_  (B_ * T_)   // 32768 rows
#define K_  8192

// Output layout in d_out (flat float32): [quantized 8388608][loss 1][idx 32768]
#define Q_ELEMS   (B_ * D_ * T_)
#define LOSS_OFF  Q_ELEMS
#define IDX_OFF   (Q_ELEMS + 1)

// Device scratch (no allocations allowed)
__device__ float g_enorm[K_];
__device__ float g_znorm[N_];
__device__ int   g_idx[N_];
__device__ float g_partial[N_ / 128];

// ---------------------------------------------------------------------------
// Kernel 1a: e_norm[k] = sum_d emb[k,d]^2.  Order irrelevant for matching
// (perturbation ~1e-13 vs ulp(256)=3e-5 grid), so use fast warp reduce.
// ---------------------------------------------------------------------------
__global__ void enorm_kernel(const float* __restrict__ emb) {
    int gw   = (blockIdx.x * blockDim.x + threadIdx.x) >> 5;
    int lane = threadIdx.x & 31;
    if (gw >= K_) return;
    const float4* row = reinterpret_cast<const float4*>(emb + (size_t)gw * D_);
    float s = 0.f;
    #pragma unroll
    for (int i = 0; i < 2; i++) {
        float4 v = row[lane + 32 * i];
        s += v.x * v.x + v.y * v.y + v.z * v.z + v.w * v.w;
    }
    #pragma unroll
    for (int o = 16; o > 0; o >>= 1) s += __shfl_xor_sync(0xffffffffu, s, o);
    if (lane == 0) g_enorm[gw] = s;
}

// ---------------------------------------------------------------------------
// Kernel 1b: z_norm[n] = sum_d z[b,d,t]^2, SEQUENTIAL over d with separately
// rounded squares (emulating XLA's elementwise-square + single-accumulator
// reduce). Thread n=(b,t); consecutive threads -> consecutive t (coalesced).
// ---------------------------------------------------------------------------
__global__ __launch_bounds__(256)
void znorm_kernel(const float* __restrict__ z) {
    int n = blockIdx.x * 256 + threadIdx.x;
    int b = n / T_;
    int t = n % T_;
    const float* base = z + (size_t)b * D_ * T_ + t;
    float s = 0.f;
    #pragma unroll 8
    for (int d = 0; d < D_; d++) {
        float v = base[(size_t)d * T_];
        s = __fadd_rn(s, __fmul_rn(v, v));   // no FMA: square rounded first
    }
    g_znorm[n] = s;
}

// ---------------------------------------------------------------------------
// Kernel 2: fused distance-GEMM + argmin.
// dist[m][k] = fl( fl(znorm[m] + enorm[k]) - fl(2 * dot) ), where dot is a
// sequential ascending-d fp32 FMA chain (bit-compatible with single-
// accumulator fp32 GEMMs: cuBLAS SIMT / Eigen).
// Block = 128 rows x all K in 128-code tiles, 8x8 per thread.
// ---------------------------------------------------------------------------
#define BM 128
#define BN 128
#define BK 16
#define TM 8
#define TN 8

__global__ __launch_bounds__(256, 2)
void vq_argmin_kernel(const float* __restrict__ z,
                      const float* __restrict__ emb,
                      float* __restrict__ d_out) {
    __shared__ float As[BK][BM];       // As[d][m] = zf[m][d]
    __shared__ float Bs[BK][BN];       // Bs[d][k]
    __shared__ float En[BN];
    __shared__ float Zn[BM];
    __shared__ float rmin[BM];
    __shared__ int   ridx[BM];

    const int n0 = blockIdx.x * BM;
    const int b  = n0 / T_;
    const int t0 = n0 % T_;
    const float* zb = z + (size_t)b * D_ * T_ + t0;   // zb[d * T_ + m]

    const int tid = threadIdx.x;
    const int tx  = tid & 15;          // code-tile column group
    const int ty  = tid >> 4;          // row group

    if (tid < BM) {
        rmin[tid] = 3.4e38f;
        ridx[tid] = 0;
        Zn[tid]   = g_znorm[n0 + tid];
    }

    // Load-index precompute
    const int a_dd = tid >> 4;         // 0..15 (d row of As)
    const int a_mq = (tid & 15) * 4;   // float4 offset in m
    const int b_kk = tid >> 1;         // 0..127 (code row)
    const int b_dq = (tid & 1) * 8;    // d offset 0 or 8

    for (int kt = 0; kt < K_; kt += BN) {
        __syncthreads();                       // prev epilogue done reading En
        if (tid < BN) En[tid] = g_enorm[kt + tid];

        float acc[TM][TN];
        #pragma unroll
        for (int i = 0; i < TM; i++)
            #pragma unroll
            for (int j = 0; j < TN; j++) acc[i][j] = 0.f;

        for (int d0 = 0; d0 < D_; d0 += BK) {
            __syncthreads();                   // prev compute done reading As/Bs
            // --- load z tile: 16 threads per d-row, 2 float4 each ---
            const float* zrow = zb + (size_t)(d0 + a_dd) * T_;
            *(float4*)&As[a_dd][a_mq]      = *(const float4*)&zrow[a_mq];
            *(float4*)&As[a_dd][64 + a_mq] = *(const float4*)&zrow[64 + a_mq];
            // --- load emb tile transposed: 1 code row per 2 threads ---
            const float* erow = emb + (size_t)(kt + b_kk) * D_ + d0 + b_dq;
            float4 v0 = *(const float4*)&erow[0];
            float4 v1 = *(const float4*)&erow[4];
            Bs[b_dq + 0][b_kk] = v0.x; Bs[b_dq + 1][b_kk] = v0.y;
            Bs[b_dq + 2][b_kk] = v0.z; Bs[b_dq + 3][b_kk] = v0.w;
            Bs[b_dq + 4][b_kk] = v1.x; Bs[b_dq + 5][b_kk] = v1.y;
            Bs[b_dq + 6][b_kk] = v1.z; Bs[b_dq + 7][b_kk] = v1.w;
            __syncthreads();
            // --- compute: strictly ascending d, one FMA chain per (i,j) ---
            #pragma unroll
            for (int d = 0; d < BK; d++) {
                float a[TM], bb[TN];
                *(float4*)&a[0]  = *(const float4*)&As[d][ty * TM];
                *(float4*)&a[4]  = *(const float4*)&As[d][ty * TM + 4];
                *(float4*)&bb[0] = *(const float4*)&Bs[d][tx * TN];
                *(float4*)&bb[4] = *(const float4*)&Bs[d][tx * TN + 4];
                #pragma unroll
                for (int i = 0; i < TM; i++)
                    #pragma unroll
                    for (int j = 0; j < TN; j++)
                        acc[i][j] = __fmaf_rn(a[i], bb[j], acc[i][j]);
            }
        }

        // --- epilogue: replicate reference rounding, per-row argmin ---
        #pragma unroll
        for (int i = 0; i < TM; i++) {
            const float zn = Zn[ty * TM + i];
            float bv = 3.4e38f;
            int   bj = 0;
            #pragma unroll
            for (int j = 0; j < TN; j++) {
                float v = __fsub_rn(__fadd_rn(zn, En[tx * TN + j]),
                                    __fmul_rn(2.f, acc[i][j]));
                if (v < bv) { bv = v; bj = j; }     // strict <: lowest j on tie
            }
            int bk = kt + tx * TN + bj;
            // reduce across the 16 tx lanes (same 16-lane half of the warp)
            #pragma unroll
            for (int o = 1; o < 16; o <<= 1) {
                float ov = __shfl_xor_sync(0xffffffffu, bv, o);
                int   ok = __shfl_xor_sync(0xffffffffu, bk, o);
                if (ov < bv || (ov == bv && ok < bk)) { bv = ov; bk = ok; }
            }
            if (tx == 0) {
                int m = ty * TM + i;
                if (bv < rmin[m]) { rmin[m] = bv; ridx[m] = bk; }  // earlier tile wins ties
            }
        }
    }

    __syncthreads();
    if (tid < BM) {
        int n = n0 + tid;
        g_idx[n] = ridx[tid];
        d_out[IDX_OFF + n] = (float)ridx[tid];
    }
}

// ---------------------------------------------------------------------------
// Kernel 3: straight-through output + per-block loss partial.
// out = fl(z + fl(q - z))  -- MUST replicate, not just q (the fp32 round of
// (q - z) leaves ~ulp(z) noise that is ~1e-3 relative to q).
// ---------------------------------------------------------------------------
__global__ __launch_bounds__(256)
void gather_kernel(const float* __restrict__ z,
                   const float* __restrict__ emb,
                   float* __restrict__ d_out) {
    __shared__ int   sidx[128];
    __shared__ float red[256];
    const int n0 = blockIdx.x * 128;
    const int b  = n0 / T_;
    const int t0 = n0 % T_;
    const int tid = threadIdx.x;

    if (tid < 128) sidx[tid] = g_idx[n0 + tid];
    __syncthreads();

    float local = 0.f;
    // e = d*128 + m; consecutive threads -> consecutive m (coalesced z/out)
    for (int e = tid; e < 128 * D_; e += 256) {
        int m = e & 127;
        int d = e >> 7;
        float q = emb[(size_t)sidx[m] * D_ + d];        // L2-resident gather
        size_t off = (size_t)b * D_ * T_ + (size_t)d * T_ + t0 + m;
        float zv = z[off];
        float df = __fsub_rn(q, zv);                    // fl(q - z)
        d_out[off] = __fadd_rn(zv, df);                 // fl(z + fl(q - z))
        local = __fmaf_rn(df, df, local);
    }
    red[tid] = local;
    __syncthreads();
    #pragma unroll
    for (int s = 128; s > 0; s >>= 1) {
        if (tid < s) red[tid] += red[tid + s];
        __syncthreads();
    }
    if (tid == 0) g_partial[blockIdx.x] = red[0];
}

// ---------------------------------------------------------------------------
// Kernel 4: loss = 1.25 * mean((q - z)^2)   (deterministic tree reduce)
// ---------------------------------------------------------------------------
__global__ void loss_kernel(float* __restrict__ d_out) {
    __shared__ float red[256];
    int tid = threadIdx.x;
    red[tid] = g_partial[tid];    // exactly 256 partials
    __syncthreads();
    #pragma unroll
    for (int s = 128; s > 0; s >>= 1) {
        if (tid < s) red[tid] += red[tid + s];
        __syncthreads();
    }
    if (tid == 0)
        d_out[LOSS_OFF] = 1.25f * red[0] / (float)((size_t)N_ * D_);
}

// ---------------------------------------------------------------------------
extern "C" void kernel_launch(void* const* d_in, const int* in_sizes, int n_in,
                              void* d_out, int out_size) {
    const float* z   = (const float*)d_in[0];
    const float* emb = (const float*)d_in[1];
    float* out = (float*)d_out;
    (void)in_sizes; (void)n_in; (void)out_size;

    enorm_kernel<<<K_ * 32 / 256, 256>>>(emb);
    znorm_kernel<<<N_ / 256, 256>>>(z);
    vq_argmin_kernel<<<N_ / BM, 256>>>(z, emb, out);
    gather_kernel<<<N_ / 128, 256>>>(z, emb, out);
    loss_kernel<<<1, 256>>>(out);
}